// round 1
// baseline (speedup 1.0000x reference)
#include <cuda_runtime.h>
#include <cstddef>

#define NN      100000
#define EE      1200000
#define NFEAT_K 128
#define NHID    64
#define NCLASS  16

// Scratch: ~25.6MB each. __device__ globals (no runtime allocation allowed).
__device__ float g_h0 [(size_t)NN * NHID];   // h = x@fc0_w + fc0_b (pre-ReLU)
__device__ float g_xw [(size_t)NN * NHID];   // relu(prev) @ conv_w[i]
__device__ float g_bufA[(size_t)NN * NHID];  // layer outputs (ping)
__device__ float g_bufB[(size_t)NN * NHID];  // layer outputs (pong)

// ---------------------------------------------------------------------------
// Generic row-parallel GEMM: out[r,:] = act(in[r,:]) @ W[K,N] + b
// One thread per row, W staged in smem (warp-uniform broadcast reads).
// ---------------------------------------------------------------------------
template<int K, int N, bool RELU_IN>
__global__ __launch_bounds__(256)
void gemm_bias_kernel(const float* __restrict__ in,
                      const float* __restrict__ W,
                      const float* __restrict__ b,
                      float* __restrict__ out)
{
    __shared__ float Ws[K * N];
    __shared__ float bs[N];
    for (int i = threadIdx.x; i < K * N; i += 256) Ws[i] = W[i];
    for (int i = threadIdx.x; i < N;     i += 256) bs[i] = b[i];
    __syncthreads();

    int row = blockIdx.x * 256 + threadIdx.x;
    if (row >= NN) return;

    float4 acc[N / 4];
    const float4* b4 = (const float4*)bs;
#pragma unroll
    for (int n = 0; n < N / 4; n++) acc[n] = b4[n];

    const float4* inr = (const float4*)(in + (size_t)row * K);
#pragma unroll 2
    for (int k4 = 0; k4 < K / 4; k4++) {
        float4 xv = __ldg(inr + k4);
        float xs[4];
        if (RELU_IN) {
            xs[0] = fmaxf(xv.x, 0.f); xs[1] = fmaxf(xv.y, 0.f);
            xs[2] = fmaxf(xv.z, 0.f); xs[3] = fmaxf(xv.w, 0.f);
        } else {
            xs[0] = xv.x; xs[1] = xv.y; xs[2] = xv.z; xs[3] = xv.w;
        }
#pragma unroll
        for (int kk = 0; kk < 4; kk++) {
            const float4* w4 = (const float4*)(Ws + (size_t)(k4 * 4 + kk) * N);
#pragma unroll
            for (int n = 0; n < N / 4; n++) {
                float4 w = w4[n];
                acc[n].x = fmaf(xs[kk], w.x, acc[n].x);
                acc[n].y = fmaf(xs[kk], w.y, acc[n].y);
                acc[n].z = fmaf(xs[kk], w.z, acc[n].z);
                acc[n].w = fmaf(xs[kk], w.w, acc[n].w);
            }
        }
    }

    float4* o = (float4*)(out + (size_t)row * N);
#pragma unroll
    for (int n = 0; n < N / 4; n++) o[n] = acc[n];
}

// ---------------------------------------------------------------------------
// Per-layer dense part, fused:
//   xw[r,:]      = relu(in[r,:]) @ W          (SpMM operand)
//   outinit[r,:] = 0.1*h0[r,:] + cb[:]        (SpMM accumulator pre-init)
// (theta cancels in the reference: out = support + b)
// ---------------------------------------------------------------------------
__global__ __launch_bounds__(256)
void conv_gemm_kernel(const float* __restrict__ in,
                      const float* __restrict__ W,
                      const float* __restrict__ h0,
                      const float* __restrict__ cb,
                      float* __restrict__ xw,
                      float* __restrict__ outinit)
{
    __shared__ float Ws[NHID * NHID];
    __shared__ float cbs[NHID];
    for (int i = threadIdx.x; i < NHID * NHID; i += 256) Ws[i] = W[i];
    if (threadIdx.x < NHID) cbs[threadIdx.x] = cb[threadIdx.x];
    __syncthreads();

    int row = blockIdx.x * 256 + threadIdx.x;
    if (row >= NN) return;

    float4 acc[16];
#pragma unroll
    for (int n = 0; n < 16; n++) acc[n] = make_float4(0.f, 0.f, 0.f, 0.f);

    const float4* inr = (const float4*)(in + (size_t)row * NHID);
#pragma unroll 2
    for (int k4 = 0; k4 < 16; k4++) {
        float4 xv = __ldg(inr + k4);
        float xs[4] = { fmaxf(xv.x, 0.f), fmaxf(xv.y, 0.f),
                        fmaxf(xv.z, 0.f), fmaxf(xv.w, 0.f) };
#pragma unroll
        for (int kk = 0; kk < 4; kk++) {
            const float4* w4 = (const float4*)(Ws + (size_t)(k4 * 4 + kk) * NHID);
#pragma unroll
            for (int n = 0; n < 16; n++) {
                float4 w = w4[n];
                acc[n].x = fmaf(xs[kk], w.x, acc[n].x);
                acc[n].y = fmaf(xs[kk], w.y, acc[n].y);
                acc[n].z = fmaf(xs[kk], w.z, acc[n].z);
                acc[n].w = fmaf(xs[kk], w.w, acc[n].w);
            }
        }
    }

    float4*       xo  = (float4*)(xw + (size_t)row * NHID);
    const float4* h0r = (const float4*)(h0 + (size_t)row * NHID);
    float4*       oi  = (float4*)(outinit + (size_t)row * NHID);
    const float4* cb4 = (const float4*)cbs;
#pragma unroll
    for (int n = 0; n < 16; n++) {
        xo[n] = acc[n];
        float4 h = __ldg(h0r + n);
        float4 c = cb4[n];
        oi[n] = make_float4(fmaf(0.1f, h.x, c.x), fmaf(0.1f, h.y, c.y),
                            fmaf(0.1f, h.z, c.z), fmaf(0.1f, h.w, c.w));
    }
}

// ---------------------------------------------------------------------------
// SpMM scatter: out[rows[e],:] += 0.9 * vals[e] * xw[cols[e],:]
// 16 threads per edge, each handles one float4 (coalesced 256B gather),
// vectorized float4 atomicAdd (sm_90+) -> 1 L2 red-op per 16 bytes.
// ---------------------------------------------------------------------------
__global__ __launch_bounds__(256)
void spmm_scatter_kernel(const int*   __restrict__ rows,
                         const int*   __restrict__ cols,
                         const float* __restrict__ vals,
                         const float* __restrict__ xw,
                         float*       __restrict__ out)
{
    long long tid = (long long)blockIdx.x * 256 + threadIdx.x;
    int e = (int)(tid >> 4);
    if (e >= EE) return;
    int j = (int)(tid & 15);

    int   c = __ldg(cols + e);
    int   r = __ldg(rows + e);
    float v = 0.9f * __ldg(vals + e);

    float4 xv = __ldg((const float4*)(xw + (size_t)c * NHID) + j);
    float4 m  = make_float4(v * xv.x, v * xv.y, v * xv.z, v * xv.w);

    float4* dst = (float4*)(out + (size_t)r * NHID) + j;
    atomicAdd(dst, m);   // vector red.global to L2
}

// ---------------------------------------------------------------------------
extern "C" void kernel_launch(void* const* d_in, const int* in_sizes, int n_in,
                              void* d_out, int out_size)
{
    const float* x        = (const float*)d_in[0];
    const int*   adj_rows = (const int*)  d_in[1];
    const int*   adj_cols = (const int*)  d_in[2];
    const float* adj_vals = (const float*)d_in[3];
    const float* fc0_w    = (const float*)d_in[4];
    const float* fc0_b    = (const float*)d_in[5];
    const float* conv_w   = (const float*)d_in[6];
    const float* conv_b   = (const float*)d_in[7];
    const float* fc1_w    = (const float*)d_in[8];
    const float* fc1_b    = (const float*)d_in[9];
    float* out = (float*)d_out;

    float *h0p, *xwp, *ap, *bp;
    cudaGetSymbolAddress((void**)&h0p, g_h0);
    cudaGetSymbolAddress((void**)&xwp, g_xw);
    cudaGetSymbolAddress((void**)&ap,  g_bufA);
    cudaGetSymbolAddress((void**)&bp,  g_bufB);

    const int ROW_BLOCKS  = (NN + 255) / 256;
    const int EDGE_BLOCKS = (int)(((long long)EE * 16 + 255) / 256);

    // fc0: h0 = x @ fc0_w + fc0_b   (pre-ReLU; ReLU applied at consumers)
    gemm_bias_kernel<NFEAT_K, NHID, false><<<ROW_BLOCKS, 256>>>(x, fc0_w, fc0_b, h0p);

    // 4 GCNII layers; ping-pong bufA/bufB, layer-0 input is h0.
    float* prev = h0p;
    float* bufs[2] = { ap, bp };
    for (int i = 0; i < 4; i++) {
        float* next = bufs[i & 1];
        conv_gemm_kernel<<<ROW_BLOCKS, 256>>>(
            prev, conv_w + (size_t)i * NHID * NHID, h0p, conv_b + (size_t)i * NHID,
            xwp, next);
        spmm_scatter_kernel<<<EDGE_BLOCKS, 256>>>(adj_rows, adj_cols, adj_vals, xwp, next);
        prev = next;
    }

    // fc1: out = relu(prev) @ fc1_w + fc1_b
    gemm_bias_kernel<NHID, NCLASS, true><<<ROW_BLOCKS, 256>>>(prev, fc1_w, fc1_b, out);
}